// round 13
// baseline (speedup 1.0000x reference)
#include <cuda_runtime.h>
#include <cuda.h>
#include <cstdint>

// Bilinear flow warp: TMA-filled fp32 SMEM row strips, mbarrier double-buffered
// across the channel loop; per-lane work is ONLY gather LDS + blend + store.
// R13: cap registers at 64 (launch_bounds(512,2)) so 2 blocks/SM co-reside —
// R12 compiled to 100 regs -> 1 block/SM -> occupancy-starved (24.9%).
//   img: [B=8, C=16, H=512, W=512] f32
//   flo: [B=8, 2,   H=512, W=512] f32
//   out: [B=8, C=16, H=512, W=512] f32

#define B_    8
#define C_    16
#define H_    512
#define W_    512
#define HW_   (H_ * W_)
#define TY    8
#define HALO  4
#define TROWS 16
#define THREADS 512
#define TILE_FLOATS (TROWS * W_)        // 8192
#define TILE_BYTES  (TILE_FLOATS * 4)   // 32768
#define SMEM_BYTES  (2 * TILE_BYTES + 64)
#define FB_BIT (1 << 22)

__device__ __forceinline__ void mbar_init(uint32_t a, uint32_t cnt) {
    asm volatile("mbarrier.init.shared.b64 [%0], %1;" :: "r"(a), "r"(cnt) : "memory");
}
__device__ __forceinline__ void mbar_expect(uint32_t a, uint32_t bytes) {
    asm volatile("mbarrier.arrive.expect_tx.shared.b64 _, [%0], %1;"
                 :: "r"(a), "r"(bytes) : "memory");
}
__device__ __forceinline__ void mbar_wait(uint32_t a, int ph) {
    asm volatile(
        "{\n\t.reg .pred P;\n"
        "W%=:\n\t"
        "mbarrier.try_wait.parity.acquire.cta.shared::cta.b64 P, [%0], %1, 0x989680;\n\t"
        "@P bra D%=;\n\t"
        "bra W%=;\n"
        "D%=:\n\t}"
        :: "r"(a), "r"(ph) : "memory");
}
__device__ __forceinline__ void tma4d(uint32_t dst, const CUtensorMap* m,
                                      int c0, int c1, int c2, int c3, uint32_t mbar) {
    asm volatile(
        "cp.async.bulk.tensor.4d.shared::cta.global.tile.mbarrier::complete_tx::bytes "
        "[%0], [%1, {%2, %3, %4, %5}], [%6];"
        :: "r"(dst), "l"(m), "r"(c0), "r"(c1), "r"(c2), "r"(c3), "r"(mbar) : "memory");
}

__global__ __launch_bounds__(THREADS, 2) void warp_bilinear_tma_kernel(
    const __grid_constant__ CUtensorMap tmap,
    const float* __restrict__ img,
    const float* __restrict__ flo,
    float* __restrict__ out)
{
    extern __shared__ float smem[];     // [2][TILE_FLOATS] + mbarriers
    const uint32_t smem_u32 = (uint32_t)__cvta_generic_to_shared(smem);
    const uint32_t mb = smem_u32 + 2 * TILE_BYTES;   // two 8B mbarriers

    const int bx = blockIdx.x;          // 0..511
    const int b  = bx >> 6;             // 64 strips per batch
    const int h0 = (bx & 63) * TY;
    const int w  = threadIdx.x;
    const int row_lo = h0 - HALO;
    const int plane0 = b * C_;          // z-coord of channel 0

    if (threadIdx.x == 0) {
        mbar_init(mb, 1);
        mbar_init(mb + 8, 1);
        asm volatile("fence.proxy.async.shared::cta;" ::: "memory");
    }
    __syncthreads();

    if (threadIdx.x == 0) {             // kick off channel 0 fill
        mbar_expect(mb, TILE_BYTES);
        tma4d(smem_u32, &tmap, 0, 0, row_lo, plane0, mb);
    }

    // ---- Per-pixel geometry (overlaps TMA ch0) ----
    float xw[TY], yw[TY];
    int   pk[TY];                       // x0 | f2<<10 | dx<<20 | dy<<21 | fb<<22

    const int flo_b = (b * 2) * HW_;
    #pragma unroll
    for (int i = 0; i < TY; i++) {
        int h = h0 + i;
        float fx = __ldg(flo + flo_b + h * W_ + w);
        float fy = __ldg(flo + flo_b + HW_ + h * W_ + w);

        float px = (float)w + fx;
        float py = (float)h + fy;
        float x0f = floorf(px);
        float y0f = floorf(py);
        xw[i] = px - x0f;               // weights from UNclamped floor
        yw[i] = py - y0f;

        int x0 = (int)fminf(fmaxf(x0f,        0.0f), (float)(W_ - 1));
        int x1 = (int)fminf(fmaxf(x0f + 1.0f, 0.0f), (float)(W_ - 1));
        int y0 = (int)fminf(fmaxf(y0f,        0.0f), (float)(H_ - 1));
        int y1 = (int)fminf(fmaxf(y0f + 1.0f, 0.0f), (float)(H_ - 1));

        int dx = x1 - x0;
        int dy = y1 - y0;
        int fb = (y0 < row_lo) || (y1 > row_lo + TROWS - 1);
        int f2 = fb ? y0 : (y0 - row_lo);
        pk[i] = x0 | (f2 << 10) | (dx << 20) | (dy << 21) | (fb ? FB_BIT : 0);
    }

    const float* bimg = img + (size_t)b * C_ * HW_;
    int ph0 = 0, ph1 = 0;

    for (int c = 0; c < C_; c++) {
        const int s = c & 1;
        // Issue fill for c+1 into the other buffer (its readers finished at
        // the __syncthreads ending iteration c-1).
        if (threadIdx.x == 0 && c + 1 < C_) {
            uint32_t mbn = mb + 8 * (1 - s);
            mbar_expect(mbn, TILE_BYTES);
            tma4d(smem_u32 + (1 - s) * TILE_BYTES, &tmap,
                  0, 0, row_lo, plane0 + c + 1, mbn);
        }
        // Wait for buffer s (channel c)
        if (s == 0) { mbar_wait(mb, ph0);     ph0 ^= 1; }
        else        { mbar_wait(mb + 8, ph1); ph1 ^= 1; }

        const float* tbuf   = smem + s * TILE_FLOATS;
        const float* plane  = bimg + (size_t)c * HW_;
        float*       oplane = out + ((size_t)(b * C_ + c)) * HW_;

        #pragma unroll
        for (int i = 0; i < TY; i++) {
            int p  = pk[i];
            int x0 = p & 1023;
            int f2 = (p >> 10) & 1023;
            int dx = (p >> 20) & 1;
            int dy = (p >> 21) & 1;

            float Ia, Ib, Ic, Id;
            if (!(p & FB_BIT)) {
                int base  = f2 * W_ + x0;
                int base1 = base + dy * W_;
                Ia = tbuf[base];
                Ic = tbuf[base + dx];
                Ib = tbuf[base1];
                Id = tbuf[base1 + dx];
            } else {                     // f2 = global y0 (clamped)
                const float* g  = plane + f2 * W_ + x0;
                const float* g1 = g + dy * W_;
                Ia = __ldg(g);  Ic = __ldg(g + dx);
                Ib = __ldg(g1); Id = __ldg(g1 + dx);
            }

            float xwv = xw[i], ywv = yw[i];
            float wa = (1.0f - xwv) * (1.0f - ywv);
            float wb = (1.0f - xwv) * ywv;
            float wc = xwv * (1.0f - ywv);
            float wd = xwv * ywv;

            float r = wa * Ia;
            r = fmaf(wb, Ib, r);
            r = fmaf(wc, Ic, r);
            r = fmaf(wd, Id, r);
            oplane[(h0 + i) * W_ + w] = r;
        }

        __syncthreads();                 // buffer s fully read before it is
                                         // refilled at iteration c+1
    }
}

// ---- Fallback: proven direct-gather kernel (R1), used only if the TMA
// ---- encode entry point is unavailable.
__global__ __launch_bounds__(256) void warp_bilinear_direct_kernel(
    const float* __restrict__ img,
    const float* __restrict__ flo,
    float* __restrict__ out)
{
    int idx = blockIdx.x * blockDim.x + threadIdx.x;
    if (idx >= B_ * HW_) return;
    int w = idx & (W_ - 1);
    int t = idx >> 9;
    int h = t & (H_ - 1);
    int b = t >> 9;

    int flo_base = ((b * 2) * H_ + h) * W_ + w;
    float fx = __ldg(flo + flo_base);
    float fy = __ldg(flo + flo_base + HW_);
    float px = (float)w + fx;
    float py = (float)h + fy;
    float x0f = floorf(px), y0f = floorf(py);
    float xw = px - x0f, yw = py - y0f;
    int x0 = (int)fminf(fmaxf(x0f,        0.0f), (float)(W_ - 1));
    int x1 = (int)fminf(fmaxf(x0f + 1.0f, 0.0f), (float)(W_ - 1));
    int y0 = (int)fminf(fmaxf(y0f,        0.0f), (float)(H_ - 1));
    int y1 = (int)fminf(fmaxf(y0f + 1.0f, 0.0f), (float)(H_ - 1));
    float wa = (1.0f - xw) * (1.0f - yw);
    float wb = (1.0f - xw) * yw;
    float wc = xw * (1.0f - yw);
    float wd = xw * yw;
    int o00 = y0 * W_ + x0, o10 = y1 * W_ + x0;
    int o01 = y0 * W_ + x1, o11 = y1 * W_ + x1;
    const float* ibase = img + (size_t)b * C_ * HW_;
    float* obase = out + (size_t)b * C_ * HW_ + h * W_ + w;
    #pragma unroll
    for (int c = 0; c < C_; c++) {
        const float* p = ibase + c * HW_;
        float Ia = __ldg(p + o00), Ib = __ldg(p + o10);
        float Ic = __ldg(p + o01), Id = __ldg(p + o11);
        obase[c * HW_] = wa * Ia + wb * Ib + wc * Ic + wd * Id;
    }
}

typedef CUresult (*PFN_encode)(CUtensorMap*, CUtensorMapDataType, cuuint32_t,
                               void*, const cuuint64_t*, const cuuint64_t*,
                               const cuuint32_t*, const cuuint32_t*,
                               CUtensorMapInterleave, CUtensorMapSwizzle,
                               CUtensorMapL2promotion, CUtensorMapFloatOOBfill);

extern "C" void kernel_launch(void* const* d_in, const int* in_sizes, int n_in,
                              void* d_out, int out_size)
{
    const float* img = (const float*)d_in[0];
    const float* flo = (const float*)d_in[1];
    float* out = (float*)d_out;

    // Resolve cuTensorMapEncodeTiled through the runtime (no -lcuda needed).
    void* fn = nullptr;
    cudaDriverEntryPointQueryResult qres = cudaDriverEntryPointSymbolNotFound;
    cudaError_t e = cudaGetDriverEntryPoint("cuTensorMapEncodeTiled", &fn,
                                            cudaEnableDefault, &qres);

    bool tma_ok = (e == cudaSuccess && qres == cudaDriverEntryPointSuccess && fn);
    CUtensorMap tmap;
    if (tma_ok) {
        // 4D view of img: dims {256 (x-lo), 2 (x-hi), 512 (y), 128 (b*c)}
        cuuint64_t dims[4]    = {256, 2, 512, (cuuint64_t)(B_ * C_)};
        cuuint64_t strides[3] = {256 * 4, (cuuint64_t)W_ * 4,
                                 (cuuint64_t)HW_ * 4};          // bytes
        cuuint32_t box[4]     = {256, 2, TROWS, 1};
        cuuint32_t estr[4]    = {1, 1, 1, 1};
        CUresult r = ((PFN_encode)fn)(&tmap, CU_TENSOR_MAP_DATA_TYPE_FLOAT32, 4,
                                      (void*)img, dims, strides, box, estr,
                                      CU_TENSOR_MAP_INTERLEAVE_NONE,
                                      CU_TENSOR_MAP_SWIZZLE_NONE,
                                      CU_TENSOR_MAP_L2_PROMOTION_L2_128B,
                                      CU_TENSOR_MAP_FLOAT_OOB_FILL_NONE);
        if (r != CUDA_SUCCESS) tma_ok = false;
    }

    if (tma_ok) {
        cudaFuncSetAttribute(warp_bilinear_tma_kernel,
                             cudaFuncAttributeMaxDynamicSharedMemorySize,
                             SMEM_BYTES);
        warp_bilinear_tma_kernel<<<B_ * (H_ / TY), THREADS, SMEM_BYTES>>>(
            tmap, img, flo, out);
    } else {
        const int total = B_ * HW_;
        warp_bilinear_direct_kernel<<<(total + 255) / 256, 256>>>(img, flo, out);
    }
}

// round 14
// speedup vs baseline: 1.2467x; 1.2467x over previous
#include <cuda_runtime.h>
#include <cuda.h>
#include <cstdint>

// Bilinear flow warp: TMA-filled fp32 SMEM strips, TWO channels per buffer.
// 8 pipeline iterations; each gather phase blends 2 channels from one buffer
// (8 independent LDS per pixel) to hide LDS latency with ILP at low occupancy.
//   img: [B=8, C=16, H=512, W=512] f32
//   flo: [B=8, 2,   H=512, W=512] f32
//   out: [B=8, C=16, H=512, W=512] f32

#define B_    8
#define C_    16
#define H_    512
#define W_    512
#define HW_   (H_ * W_)
#define TY    8
#define HALO  4
#define TROWS 16
#define THREADS 512
#define TILE_FLOATS (TROWS * W_)          // 8192 per channel
#define PAIR_FLOATS (2 * TILE_FLOATS)     // 16384 per buffer (2 channels)
#define PAIR_BYTES  (PAIR_FLOATS * 4)     // 65536
#define SMEM_BYTES  (2 * PAIR_BYTES + 64)
#define FB_BIT (1 << 22)

__device__ __forceinline__ void mbar_init(uint32_t a, uint32_t cnt) {
    asm volatile("mbarrier.init.shared.b64 [%0], %1;" :: "r"(a), "r"(cnt) : "memory");
}
__device__ __forceinline__ void mbar_expect(uint32_t a, uint32_t bytes) {
    asm volatile("mbarrier.arrive.expect_tx.shared.b64 _, [%0], %1;"
                 :: "r"(a), "r"(bytes) : "memory");
}
__device__ __forceinline__ void mbar_wait(uint32_t a, int ph) {
    asm volatile(
        "{\n\t.reg .pred P;\n"
        "W%=:\n\t"
        "mbarrier.try_wait.parity.acquire.cta.shared::cta.b64 P, [%0], %1, 0x989680;\n\t"
        "@P bra D%=;\n\t"
        "bra W%=;\n"
        "D%=:\n\t}"
        :: "r"(a), "r"(ph) : "memory");
}
__device__ __forceinline__ void tma4d(uint32_t dst, const CUtensorMap* m,
                                      int c0, int c1, int c2, int c3, uint32_t mbar) {
    asm volatile(
        "cp.async.bulk.tensor.4d.shared::cta.global.tile.mbarrier::complete_tx::bytes "
        "[%0], [%1, {%2, %3, %4, %5}], [%6];"
        :: "r"(dst), "l"(m), "r"(c0), "r"(c1), "r"(c2), "r"(c3), "r"(mbar) : "memory");
}

__global__ __launch_bounds__(THREADS) void warp_bilinear_tma_kernel(
    const __grid_constant__ CUtensorMap tmap,
    const float* __restrict__ img,
    const float* __restrict__ flo,
    float* __restrict__ out)
{
    extern __shared__ float smem[];       // [2][PAIR_FLOATS] + mbarriers
    const uint32_t smem_u32 = (uint32_t)__cvta_generic_to_shared(smem);
    const uint32_t mb = smem_u32 + 2 * PAIR_BYTES;   // two 8B mbarriers

    const int bx = blockIdx.x;            // 0..511
    const int b  = bx >> 6;               // 64 strips per batch
    const int h0 = (bx & 63) * TY;
    const int w  = threadIdx.x;
    const int row_lo = h0 - HALO;
    const int plane0 = b * C_;            // z-coord of channel 0

    if (threadIdx.x == 0) {
        mbar_init(mb, 1);
        mbar_init(mb + 8, 1);
        asm volatile("fence.proxy.async.shared::cta;" ::: "memory");
    }
    __syncthreads();

    if (threadIdx.x == 0) {               // kick off fill of channels {0,1}
        mbar_expect(mb, PAIR_BYTES);
        tma4d(smem_u32, &tmap, 0, 0, row_lo, plane0, mb);
    }

    // ---- Per-pixel geometry (overlaps TMA of pair 0) ----
    // pk: tile addr scheme (fb=0): base(13b) | dx<<13 | dy<<14
    //     global scheme (fb=1): x0 | y0<<10 | dx<<20 | dy<<21 | FB_BIT
    float xw[TY], yw[TY];
    int   pk[TY];

    const int flo_b = (b * 2) * HW_;
    #pragma unroll
    for (int i = 0; i < TY; i++) {
        int h = h0 + i;
        float fx = __ldg(flo + flo_b + h * W_ + w);
        float fy = __ldg(flo + flo_b + HW_ + h * W_ + w);

        float px = (float)w + fx;
        float py = (float)h + fy;
        float x0f = floorf(px);
        float y0f = floorf(py);
        xw[i] = px - x0f;                 // weights from UNclamped floor
        yw[i] = py - y0f;

        int x0 = (int)fminf(fmaxf(x0f,        0.0f), (float)(W_ - 1));
        int x1 = (int)fminf(fmaxf(x0f + 1.0f, 0.0f), (float)(W_ - 1));
        int y0 = (int)fminf(fmaxf(y0f,        0.0f), (float)(H_ - 1));
        int y1 = (int)fminf(fmaxf(y0f + 1.0f, 0.0f), (float)(H_ - 1));

        int dx = x1 - x0;
        int dy = y1 - y0;
        int fb = (y0 < row_lo) || (y1 > row_lo + TROWS - 1);
        pk[i] = fb ? (x0 | (y0 << 10) | (dx << 20) | (dy << 21) | FB_BIT)
                   : (((y0 - row_lo) * W_ + x0) | (dx << 13) | (dy << 14));
    }

    const float* bimg = img + (size_t)b * C_ * HW_;
    int ph0 = 0, ph1 = 0;

    for (int t = 0; t < C_ / 2; t++) {    // 8 channel pairs
        const int s = t & 1;
        if (threadIdx.x == 0 && t + 1 < C_ / 2) {
            uint32_t mbn = mb + 8 * (1 - s);
            mbar_expect(mbn, PAIR_BYTES);
            tma4d(smem_u32 + (1 - s) * PAIR_BYTES, &tmap,
                  0, 0, row_lo, plane0 + 2 * (t + 1), mbn);
        }
        if (s == 0) { mbar_wait(mb, ph0);     ph0 ^= 1; }
        else        { mbar_wait(mb + 8, ph1); ph1 ^= 1; }

        const float* tA = smem + s * PAIR_FLOATS;          // channel 2t
        const float* tB = tA + TILE_FLOATS;                // channel 2t+1
        const float* pA = bimg + (size_t)(2 * t)     * HW_;
        const float* pB = bimg + (size_t)(2 * t + 1) * HW_;
        float* oA = out + ((size_t)(b * C_ + 2 * t))     * HW_ + h0 * W_ + w;
        float* oB = out + ((size_t)(b * C_ + 2 * t + 1)) * HW_ + h0 * W_ + w;

        #pragma unroll
        for (int i = 0; i < TY; i++) {
            int p = pk[i];

            float Ia0, Ib0, Ic0, Id0, Ia1, Ib1, Ic1, Id1;
            if (!(p & FB_BIT)) {
                int base  = p & 8191;
                int ic    = base + ((p >> 13) & 1);
                int base1 = base + (((p >> 14) & 1) << 9);   // + dy*512
                int id    = ic   + (((p >> 14) & 1) << 9);
                Ia0 = tA[base];  Ic0 = tA[ic];
                Ib0 = tA[base1]; Id0 = tA[id];
                Ia1 = tB[base];  Ic1 = tB[ic];
                Ib1 = tB[base1]; Id1 = tB[id];
            } else {
                int x0 = p & 1023;
                int y0 = (p >> 10) & 1023;
                int dx = (p >> 20) & 1;
                int dy = (p >> 21) & 1;
                int g  = y0 * W_ + x0;
                int g1 = g + dy * W_;
                Ia0 = __ldg(pA + g);  Ic0 = __ldg(pA + g + dx);
                Ib0 = __ldg(pA + g1); Id0 = __ldg(pA + g1 + dx);
                Ia1 = __ldg(pB + g);  Ic1 = __ldg(pB + g + dx);
                Ib1 = __ldg(pB + g1); Id1 = __ldg(pB + g1 + dx);
            }

            float xwv = xw[i], ywv = yw[i];
            float wa = (1.0f - xwv) * (1.0f - ywv);
            float wb = (1.0f - xwv) * ywv;
            float wc = xwv * (1.0f - ywv);
            float wd = xwv * ywv;

            float r0 = wa * Ia0;
            float r1 = wa * Ia1;
            r0 = fmaf(wb, Ib0, r0);   r1 = fmaf(wb, Ib1, r1);
            r0 = fmaf(wc, Ic0, r0);   r1 = fmaf(wc, Ic1, r1);
            r0 = fmaf(wd, Id0, r0);   r1 = fmaf(wd, Id1, r1);
            oA[i * W_] = r0;
            oB[i * W_] = r1;
        }

        __syncthreads();                  // buffer s fully read before refill
    }
}

// ---- Fallback: proven direct-gather kernel (R1) ----
__global__ __launch_bounds__(256) void warp_bilinear_direct_kernel(
    const float* __restrict__ img,
    const float* __restrict__ flo,
    float* __restrict__ out)
{
    int idx = blockIdx.x * blockDim.x + threadIdx.x;
    if (idx >= B_ * HW_) return;
    int w = idx & (W_ - 1);
    int t = idx >> 9;
    int h = t & (H_ - 1);
    int b = t >> 9;

    int flo_base = ((b * 2) * H_ + h) * W_ + w;
    float fx = __ldg(flo + flo_base);
    float fy = __ldg(flo + flo_base + HW_);
    float px = (float)w + fx;
    float py = (float)h + fy;
    float x0f = floorf(px), y0f = floorf(py);
    float xw = px - x0f, yw = py - y0f;
    int x0 = (int)fminf(fmaxf(x0f,        0.0f), (float)(W_ - 1));
    int x1 = (int)fminf(fmaxf(x0f + 1.0f, 0.0f), (float)(W_ - 1));
    int y0 = (int)fminf(fmaxf(y0f,        0.0f), (float)(H_ - 1));
    int y1 = (int)fminf(fmaxf(y0f + 1.0f, 0.0f), (float)(H_ - 1));
    float wa = (1.0f - xw) * (1.0f - yw);
    float wb = (1.0f - xw) * yw;
    float wc = xw * (1.0f - yw);
    float wd = xw * yw;
    int o00 = y0 * W_ + x0, o10 = y1 * W_ + x0;
    int o01 = y0 * W_ + x1, o11 = y1 * W_ + x1;
    const float* ibase = img + (size_t)b * C_ * HW_;
    float* obase = out + (size_t)b * C_ * HW_ + h * W_ + w;
    #pragma unroll
    for (int c = 0; c < C_; c++) {
        const float* p = ibase + c * HW_;
        float Ia = __ldg(p + o00), Ib = __ldg(p + o10);
        float Ic = __ldg(p + o01), Id = __ldg(p + o11);
        obase[c * HW_] = wa * Ia + wb * Ib + wc * Ic + wd * Id;
    }
}

typedef CUresult (*PFN_encode)(CUtensorMap*, CUtensorMapDataType, cuuint32_t,
                               void*, const cuuint64_t*, const cuuint64_t*,
                               const cuuint32_t*, const cuuint32_t*,
                               CUtensorMapInterleave, CUtensorMapSwizzle,
                               CUtensorMapL2promotion, CUtensorMapFloatOOBfill);

extern "C" void kernel_launch(void* const* d_in, const int* in_sizes, int n_in,
                              void* d_out, int out_size)
{
    const float* img = (const float*)d_in[0];
    const float* flo = (const float*)d_in[1];
    float* out = (float*)d_out;

    void* fn = nullptr;
    cudaDriverEntryPointQueryResult qres = cudaDriverEntryPointSymbolNotFound;
    cudaError_t e = cudaGetDriverEntryPoint("cuTensorMapEncodeTiled", &fn,
                                            cudaEnableDefault, &qres);

    bool tma_ok = (e == cudaSuccess && qres == cudaDriverEntryPointSuccess && fn);
    CUtensorMap tmap;
    if (tma_ok) {
        // 4D view of img: dims {256 (x-lo), 2 (x-hi), 512 (y), 128 (b*c)}
        cuuint64_t dims[4]    = {256, 2, 512, (cuuint64_t)(B_ * C_)};
        cuuint64_t strides[3] = {256 * 4, (cuuint64_t)W_ * 4,
                                 (cuuint64_t)HW_ * 4};
        cuuint32_t box[4]     = {256, 2, TROWS, 2};   // 2 channel planes
        cuuint32_t estr[4]    = {1, 1, 1, 1};
        CUresult r = ((PFN_encode)fn)(&tmap, CU_TENSOR_MAP_DATA_TYPE_FLOAT32, 4,
                                      (void*)img, dims, strides, box, estr,
                                      CU_TENSOR_MAP_INTERLEAVE_NONE,
                                      CU_TENSOR_MAP_SWIZZLE_NONE,
                                      CU_TENSOR_MAP_L2_PROMOTION_L2_128B,
                                      CU_TENSOR_MAP_FLOAT_OOB_FILL_NONE);
        if (r != CUDA_SUCCESS) tma_ok = false;
    }

    if (tma_ok) {
        cudaFuncSetAttribute(warp_bilinear_tma_kernel,
                             cudaFuncAttributeMaxDynamicSharedMemorySize,
                             SMEM_BYTES);
        warp_bilinear_tma_kernel<<<B_ * (H_ / TY), THREADS, SMEM_BYTES>>>(
            tmap, img, flo, out);
    } else {
        const int total = B_ * HW_;
        warp_bilinear_direct_kernel<<<(total + 255) / 256, 256>>>(img, flo, out);
    }
}